// round 6
// baseline (speedup 1.0000x reference)
#include <cuda_runtime.h>
#include <cstdint>

#define BATCH 16
#define Hn 512
#define Wn 512
#define WPR 16            // 32-bit words per row
#define ST 17             // smem row stride (bank padding)
#define CSIZE 4           // cluster size (CTAs per image)
#define CROWS (Hn / CSIZE)   // 128 rows per CTA
#define BR (CROWS + 2)       // rows incl. top/bottom halo
#define NTHR 512             // 4 threads per row

// counting-stage constants
#define SLAB 32
#define SROWS (SLAB + 6)     // 38-row window
#define CW 17                // counting smem stride
#define NELE (SROWS * WPR)   // 608 words per window per mask

__device__ uint32_t g_skel[2][BATCH][Hn][WPR];
__device__ int g_counts[BATCH][3];     // written (not accumulated) by batch-last CTA
__device__ int g_bt[BATCH];            // per-batch arrival tickets (monotonic, %8)
__device__ int g_ticket;               // batch-completion ticket (monotonic, %16)

// ---------------------------------------------------------------------------
// helpers
// ---------------------------------------------------------------------------
__device__ __forceinline__ uint32_t smem_u32(const void* p) {
    uint32_t a;
    asm("{ .reg .u64 t; cvta.to.shared.u64 t, %1; cvt.u32.u64 %0, t; }"
        : "=r"(a) : "l"(p));
    return a;
}
__device__ __forceinline__ void st_cluster(uint32_t laddr, uint32_t rank, uint32_t val) {
    asm volatile(
        "{ .reg .b32 ra; mapa.shared::cluster.u32 ra, %0, %1; "
        "st.shared::cluster.u32 [ra], %2; }"
        :: "r"(laddr), "r"(rank), "r"(val) : "memory");
}
__device__ __forceinline__ uint32_t cluster_rank() {
    uint32_t r; asm("mov.u32 %0, %%cluster_ctarank;" : "=r"(r)); return r;
}
#define CLUSTER_SYNC() do { \
    asm volatile("barrier.cluster.arrive.aligned;" ::: "memory"); \
    asm volatile("barrier.cluster.wait.aligned;"   ::: "memory"); \
} while (0)

// horizontal dilations on the counting window (stride CW)
__device__ __forceinline__ uint32_t hd3(const uint32_t* M, int r, int w) {
    uint32_t p = (w > 0)       ? M[r * CW + w - 1] : 0u;
    uint32_t c =                 M[r * CW + w];
    uint32_t n = (w < WPR - 1) ? M[r * CW + w + 1] : 0u;
    uint32_t v = c;
    v |= (c >> 1) | (n << 31); v |= (c << 1) | (p >> 31);
    v |= (c >> 2) | (n << 30); v |= (c << 2) | (p >> 30);
    v |= (c >> 3) | (n << 29); v |= (c << 3) | (p >> 29);
    return v;
}
__device__ __forceinline__ uint32_t hd2(const uint32_t* M, int r, int w) {
    uint32_t p = (w > 0)       ? M[r * CW + w - 1] : 0u;
    uint32_t c =                 M[r * CW + w];
    uint32_t n = (w < WPR - 1) ? M[r * CW + w + 1] : 0u;
    uint32_t v = c;
    v |= (c >> 1) | (n << 31); v |= (c << 1) | (p >> 31);
    v |= (c >> 2) | (n << 30); v |= (c << 2) | (p >> 30);
    return v;
}
__device__ __forceinline__ uint32_t dil3w(const uint32_t* M, int r, int w) {
    // squared radius 9: dy=0 -> |dx|<=3; |dy| in {1,2} -> |dx|<=2; |dy|=3 -> dx=0
    uint32_t v = hd3(M, r, w);
    v |= hd2(M, r - 1, w) | hd2(M, r + 1, w);
    v |= hd2(M, r - 2, w) | hd2(M, r + 2, w);
    v |= M[(r - 3) * CW + w] | M[(r + 3) * CW + w];
    return v;
}

// ---------------------------------------------------------------------------
// Single fused kernel: binarize + Zhang-Suen to convergence (4-CTA cluster
// per image), then last-CTA-per-batch counting + last-batch finalize.
// ---------------------------------------------------------------------------
__global__ void __launch_bounds__(NTHR, 1) __cluster_dims__(CSIZE, 1, 1)
skel_kernel(const float* __restrict__ pred, const float* __restrict__ gt,
            float* __restrict__ out) {
    __shared__ uint32_t bufs[2][BR * ST];
    __shared__ int s_chg[2][BR];     // stamp of last change per row, by parity
    __shared__ int s_changed;        // local: max stamp with any removal
    __shared__ int c_changed;        // cluster: max stamp with any removal
    __shared__ uint32_t sP[SROWS * CW];
    __shared__ uint32_t sG[SROWS * CW];
    __shared__ int s_ticket;
    __shared__ int stp, sfp, sfn;

    const int tid = threadIdx.x;
    const uint32_t rank = cluster_rank();
    const int img = blockIdx.x >> 2;
    const int b = img & 15;
    const int m = img >> 4;          // 0 = pred, 1 = gt
    const float* in = (m ? gt : pred) + (size_t)b * Hn * Wn + (size_t)rank * CROWS * Wn;

    // init stamps, flags, halo rows (halos stay 0 forever on image edges)
    if (tid < BR) { s_chg[0][tid] = 0; s_chg[1][tid] = 0; }
    if (tid == 0) { s_changed = 0; c_changed = 0; }
    if (tid < 2 * 2 * WPR) {          // 64 halo words: 2 bufs x {row 0, row BR-1}
        int bi = tid >> 5, r = (tid >> 4) & 1, w = tid & 15;
        bufs[bi][(r ? (BR - 1) : 0) * ST + w] = 0;
    }

    // --- binarize own 128 rows into bufs[0] (warp ballots -> packed words) ---
    #pragma unroll 4
    for (int p = 0; p < (CROWS * Wn) / NTHR; ++p) {
        int idx = p * NTHR + tid;
        float v = in[idx];
        uint32_t bits = __ballot_sync(0xffffffffu, v > 0.5f);
        if ((tid & 31) == 0) {
            int r = idx >> 9;            // local row
            int w = (idx >> 5) & 15;
            bufs[0][(r + 1) * ST + w] = bits;
        }
    }
    __syncthreads();

    const int lrow  = tid >> 2;          // 0..127
    const int q     = tid & 3;
    const int wbase = q * 4;
    const int i     = lrow + 1;          // buffer row index (1..128)
    const bool topB = (lrow == 0)        && (rank > 0);
    const bool botB = (lrow == CROWS-1)  && (rank < CSIZE - 1);

    uint32_t R[4];
    #pragma unroll
    for (int w = 0; w < 4; ++w) R[w] = bufs[0][i * ST + wbase + w];

    int s = 0;
    int myLast = 0;

    for (;;) {
        ++s;
        uint32_t* cur = bufs[s & 1];
        __syncthreads();                 // (A) order prior compute's smem writes

        // ---- store phase ----
        if (myLast > s - 3) {
            #pragma unroll
            for (int w = 0; w < 4; ++w) cur[i * ST + wbase + w] = R[w];
            if (topB) {
                #pragma unroll
                for (int w = 0; w < 4; ++w)
                    st_cluster(smem_u32(&cur[(BR - 1) * ST + wbase + w]), rank - 1, R[w]);
            }
            if (botB) {
                #pragma unroll
                for (int w = 0; w < 4; ++w)
                    st_cluster(smem_u32(&cur[0 * ST + wbase + w]), rank + 1, R[w]);
            }
        }
        // transmit own-row stamp of previous sub-iteration to neighbor halo
        if (q == 0) {
            const int pp = (s - 1) & 1;
            int stamp = s_chg[pp][i];
            if (topB) st_cluster(smem_u32(&s_chg[pp][BR - 1]), rank - 1, (uint32_t)stamp);
            if (botB) st_cluster(smem_u32(&s_chg[pp][0]),      rank + 1, (uint32_t)stamp);
        }
        // broadcast "changed at s-1" to all CTAs of the cluster
        if (tid == 0 && s_changed == s - 1) {
            uint32_t a = smem_u32(&c_changed);
            #pragma unroll
            for (int c = 0; c < CSIZE; ++c) st_cluster(a, c, (uint32_t)(s - 1));
        }
        CLUSTER_SYNC();                  // (B)

        if (c_changed <= s - 3) break;   // no removal in sub-iters s-1, s-2

        // ---- compute phase ----
        const int pb = (s - 1) & 1, ps = s - 1;
        bool dirty = (s_chg[pb][i] == ps) | (s_chg[pb][i - 1] == ps) | (s_chg[pb][i + 1] == ps);
        if (!dirty) continue;

        const int sub = (s + 1) & 1;     // s odd -> sub 0 ; s even -> sub 1
        const uint32_t* rU = &cur[(i - 1) * ST];
        const uint32_t* rO = &cur[i * ST];
        const uint32_t* rD = &cur[(i + 1) * ST];

        uint32_t aP = wbase ? rU[wbase - 1] : 0u;
        uint32_t cP = wbase ? rO[wbase - 1] : 0u;
        uint32_t bP = wbase ? rD[wbase - 1] : 0u;
        uint32_t aC = rU[wbase];
        uint32_t cC = R[0];
        uint32_t bC = rD[wbase];
        uint32_t cRight = (q < 3) ? rO[wbase + 4] : 0u;

        uint32_t removed = 0;
        uint32_t nR[4];
        #pragma unroll
        for (int w = 0; w < 4; ++w) {
            const int gw = wbase + w;
            uint32_t aN = 0, bN = 0, cN;
            if (gw < WPR - 1) { aN = rU[gw + 1]; bN = rD[gw + 1]; }
            cN = (w < 3) ? R[w + 1] : cRight;

            // P2..P9 clockwise from North
            uint32_t n0 = aC;
            uint32_t n1 = (aC >> 1) | (aN << 31);
            uint32_t n2 = (cC >> 1) | (cN << 31);
            uint32_t n3 = (bC >> 1) | (bN << 31);
            uint32_t n4 = bC;
            uint32_t n5 = (bC << 1) | (bP >> 31);
            uint32_t n6 = (cC << 1) | (cP >> 31);
            uint32_t n7 = (aC << 1) | (aP >> 31);

            // A == 1 (exactly one 0->1 transition around the ring)
            uint32_t e0 = ~n0 & n1, e1 = ~n1 & n2, e2 = ~n2 & n3, e3 = ~n3 & n4;
            uint32_t e4 = ~n4 & n5, e5 = ~n5 & n6, e6 = ~n6 & n7, e7 = ~n7 & n0;
            uint32_t one = e0, more = 0;
            more |= one & e1; one |= e1;
            more |= one & e2; one |= e2;
            more |= one & e3; one |= e3;
            more |= one & e4; one |= e4;
            more |= one & e5; one |= e5;
            more |= one & e6; one |= e6;
            more |= one & e7; one |= e7;
            uint32_t A1 = one & ~more;

            // Bn >= 2
            uint32_t o2 = n0, m2 = 0;
            m2 |= o2 & n1; o2 |= n1;
            m2 |= o2 & n2; o2 |= n2;
            m2 |= o2 & n3; o2 |= n3;
            m2 |= o2 & n4; o2 |= n4;
            m2 |= o2 & n5; o2 |= n5;
            m2 |= o2 & n6; o2 |= n6;
            m2 |= o2 & n7; o2 |= n7;
            uint32_t ge2 = m2;

            // Bn <= 6 (at least 2 neighbors zero)
            uint32_t z, oz = ~n0, mz = 0;
            z = ~n1; mz |= oz & z; oz |= z;
            z = ~n2; mz |= oz & z; oz |= z;
            z = ~n3; mz |= oz & z; oz |= z;
            z = ~n4; mz |= oz & z; oz |= z;
            z = ~n5; mz |= oz & z; oz |= z;
            z = ~n6; mz |= oz & z; oz |= z;
            z = ~n7; mz |= oz & z; oz |= z;
            uint32_t le6 = mz;

            uint32_t cond = A1 & ge2 & le6;
            if (sub == 0)
                cond &= ~(n0 & n2 & n4) & ~(n2 & n4 & n6);
            else
                cond &= ~(n0 & n2 & n6) & ~(n0 & n4 & n6);

            removed |= cC & cond;
            nR[w] = cC & ~cond;

            aP = aC; aC = aN;
            cP = cC; cC = cN;
            bP = bC; bC = bN;
        }
        #pragma unroll
        for (int w = 0; w < 4; ++w) R[w] = nR[w];
        if (removed) {
            s_chg[s & 1][i] = s;
            s_changed = s;
            myLast = s;
        }
    }

    // ---- write out bit-packed skeleton from registers ----
    const int grow = (int)rank * CROWS + lrow;
    #pragma unroll
    for (int w = 0; w < 4; ++w)
        g_skel[m][b][grow][wbase + w] = R[w];

    // ---- last-CTA-per-batch counting (ticket, monotonic %8) ----
    __threadfence();
    __syncthreads();
    if (tid == 0) s_ticket = atomicAdd(&g_bt[b], 1) & 7;   // 8 CTAs per batch
    __syncthreads();
    if (s_ticket != 7) return;        // not last: done
    __threadfence();                   // acquire: see all 8 CTAs' skeleton writes

    const uint32_t* P = &g_skel[0][b][0][0];
    const uint32_t* G = &g_skel[1][b][0][0];
    int tp = 0, fp = 0, fn = 0;

    // software-pipelined slab loop: prefetch next slab while computing current
    const int e0 = tid, e1 = tid + NTHR;
    auto stage_load = [&](int slab, uint32_t& p0, uint32_t& p1,
                          uint32_t& g0, uint32_t& g1) {
        const int base = slab * SLAB - 3;
        int rr = base + (e0 >> 4), w = e0 & 15;
        bool ok = (rr >= 0) & (rr < Hn);
        p0 = ok ? P[rr * WPR + w] : 0u;
        g0 = ok ? G[rr * WPR + w] : 0u;
        p1 = 0u; g1 = 0u;
        if (e1 < NELE) {
            rr = base + (e1 >> 4); w = e1 & 15;
            ok = (rr >= 0) & (rr < Hn);
            p1 = ok ? P[rr * WPR + w] : 0u;
            g1 = ok ? G[rr * WPR + w] : 0u;
        }
    };

    uint32_t p0, p1, g0, g1, np0, np1, ng0, ng1;
    stage_load(0, p0, p1, g0, g1);
    const int rl = (tid >> 4) + 3;     // window row 3..34
    const int wc = tid & 15;

    for (int slab = 0; slab < Hn / SLAB; ++slab) {
        // store staged words
        sP[(e0 >> 4) * CW + (e0 & 15)] = p0;
        sG[(e0 >> 4) * CW + (e0 & 15)] = g0;
        if (e1 < NELE) {
            sP[(e1 >> 4) * CW + (e1 & 15)] = p1;
            sG[(e1 >> 4) * CW + (e1 & 15)] = g1;
        }
        __syncthreads();
        if (slab < Hn / SLAB - 1) stage_load(slab + 1, np0, np1, ng0, ng1);

        uint32_t dg = dil3w(sG, rl, wc);
        uint32_t dp = dil3w(sP, rl, wc);
        uint32_t pw = sP[rl * CW + wc];
        uint32_t gw = sG[rl * CW + wc];
        tp += __popc(pw & dg);
        fp += __popc(pw & ~dg);
        fn += __popc(gw & ~dp);
        __syncthreads();
        p0 = np0; p1 = np1; g0 = ng0; g1 = ng1;
    }

    if (tid == 0) { stp = 0; sfp = 0; sfn = 0; }
    __syncthreads();
    #pragma unroll
    for (int o = 16; o > 0; o >>= 1) {
        tp += __shfl_down_sync(0xffffffffu, tp, o);
        fp += __shfl_down_sync(0xffffffffu, fp, o);
        fn += __shfl_down_sync(0xffffffffu, fn, o);
    }
    if ((tid & 31) == 0) {
        atomicAdd(&stp, tp);
        atomicAdd(&sfp, fp);
        atomicAdd(&sfn, fn);
    }
    __syncthreads();

    if (tid == 0) {
        g_counts[b][0] = stp;
        g_counts[b][1] = sfp;
        g_counts[b][2] = sfn;
        __threadfence();
        int t = atomicAdd(&g_ticket, 1) & 15;    // 16 batches
        if (t == 15) {
            __threadfence();
            float s0 = 0.f, s1 = 0.f, s2 = 0.f;
            for (int bb = 0; bb < BATCH; ++bb) {
                float TP = (float)g_counts[bb][0];
                float FP = (float)g_counts[bb][1];
                float FN = (float)g_counts[bb][2];
                s0 += TP / (TP + FP + 1e-12f);
                s1 += TP / (TP + FN + 1e-12f);
                s2 += TP / (TP + FP + FN + 1e-12f);
            }
            out[0] = s0 * (1.0f / BATCH);
            out[1] = s1 * (1.0f / BATCH);
            out[2] = s2 * (1.0f / BATCH);
        }
    }
}

extern "C" void kernel_launch(void* const* d_in, const int* in_sizes, int n_in,
                              void* d_out, int out_size) {
    (void)in_sizes; (void)n_in; (void)out_size;
    const float* pred = (const float*)d_in[0];
    const float* gt   = (const float*)d_in[1];
    skel_kernel<<<2 * BATCH * CSIZE, NTHR>>>(pred, gt, (float*)d_out);
}

// round 7
// speedup vs baseline: 1.3683x; 1.3683x over previous
#include <cuda_runtime.h>
#include <cstdint>

#define BATCH 16
#define Hn 512
#define Wn 512
#define WPR 16            // 32-bit words per row
#define ST 17             // smem row stride (bank padding)
#define CSIZE 4           // cluster size (CTAs per image)
#define CROWS (Hn / CSIZE)   // 128 rows per CTA
#define BR (CROWS + 2)       // rows incl. top/bottom halo
#define NTHR 512             // 4 threads per row

// counting: each of the 8 CTAs per batch counts a 64-row strip (+3 halo)
#define STRIP 64
#define CR (STRIP + 6)       // 70-row window

__device__ uint32_t g_skel[2][BATCH][Hn][WPR];
__device__ int g_counts[BATCH][3];     // integer partials (deterministic)
__device__ int g_bt[BATCH];            // per-batch arrival tickets (monotonic, &15)
__device__ int g_ticket;               // finalize ticket (monotonic, &127)

// ---------------------------------------------------------------------------
// helpers
// ---------------------------------------------------------------------------
__device__ __forceinline__ uint32_t smem_u32(const void* p) {
    uint32_t a;
    asm("{ .reg .u64 t; cvta.to.shared.u64 t, %1; cvt.u32.u64 %0, t; }"
        : "=r"(a) : "l"(p));
    return a;
}
__device__ __forceinline__ void st_cluster(uint32_t laddr, uint32_t rank, uint32_t val) {
    asm volatile(
        "{ .reg .b32 ra; mapa.shared::cluster.u32 ra, %0, %1; "
        "st.shared::cluster.u32 [ra], %2; }"
        :: "r"(laddr), "r"(rank), "r"(val) : "memory");
}
__device__ __forceinline__ uint32_t cluster_rank() {
    uint32_t r; asm("mov.u32 %0, %%cluster_ctarank;" : "=r"(r)); return r;
}
#define CLUSTER_SYNC() do { \
    asm volatile("barrier.cluster.arrive.aligned;" ::: "memory"); \
    asm volatile("barrier.cluster.wait.aligned;"   ::: "memory"); \
} while (0)

// horizontal dilations on an ST-strided window
__device__ __forceinline__ uint32_t hd3(const uint32_t* M, int r, int w) {
    uint32_t p = (w > 0)       ? M[r * ST + w - 1] : 0u;
    uint32_t c =                 M[r * ST + w];
    uint32_t n = (w < WPR - 1) ? M[r * ST + w + 1] : 0u;
    uint32_t v = c;
    v |= (c >> 1) | (n << 31); v |= (c << 1) | (p >> 31);
    v |= (c >> 2) | (n << 30); v |= (c << 2) | (p >> 30);
    v |= (c >> 3) | (n << 29); v |= (c << 3) | (p >> 29);
    return v;
}
__device__ __forceinline__ uint32_t hd2(const uint32_t* M, int r, int w) {
    uint32_t p = (w > 0)       ? M[r * ST + w - 1] : 0u;
    uint32_t c =                 M[r * ST + w];
    uint32_t n = (w < WPR - 1) ? M[r * ST + w + 1] : 0u;
    uint32_t v = c;
    v |= (c >> 1) | (n << 31); v |= (c << 1) | (p >> 31);
    v |= (c >> 2) | (n << 30); v |= (c << 2) | (p >> 30);
    return v;
}
__device__ __forceinline__ uint32_t dil3w(const uint32_t* M, int r, int w) {
    // squared radius 9: dy=0 -> |dx|<=3; |dy| in {1,2} -> |dx|<=2; |dy|=3 -> dx=0
    uint32_t v = hd3(M, r, w);
    v |= hd2(M, r - 1, w) | hd2(M, r + 1, w);
    v |= hd2(M, r - 2, w) | hd2(M, r + 2, w);
    v |= M[(r - 3) * ST + w] | M[(r + 3) * ST + w];
    return v;
}

// ---------------------------------------------------------------------------
// Fused kernel: binarize + Zhang-Suen to convergence (4-CTA cluster per
// image), then PARALLEL per-strip counting after a per-batch spin rendezvous.
// ---------------------------------------------------------------------------
__global__ void __launch_bounds__(NTHR, 1) __cluster_dims__(CSIZE, 1, 1)
skel_kernel(const float* __restrict__ pred, const float* __restrict__ gt,
            float* __restrict__ out) {
    __shared__ uint32_t bufs[2][BR * ST];
    __shared__ int s_chg[2][BR];     // stamp of last change per row, by parity
    __shared__ int s_changed;        // local: max stamp with any removal
    __shared__ int c_changed;        // cluster: max stamp with any removal
    __shared__ int stp, sfp, sfn;

    const int tid = threadIdx.x;
    const uint32_t rank = cluster_rank();
    const int img = blockIdx.x >> 2;
    const int b = img & 15;
    const int m = img >> 4;          // 0 = pred, 1 = gt
    const float* in = (m ? gt : pred) + (size_t)b * Hn * Wn + (size_t)rank * CROWS * Wn;

    // init stamps, flags, halo rows (halos stay 0 forever on image edges)
    if (tid < BR) { s_chg[0][tid] = 0; s_chg[1][tid] = 0; }
    if (tid == 0) { s_changed = 0; c_changed = 0; }
    if (tid < 2 * 2 * WPR) {          // 64 halo words: 2 bufs x {row 0, row BR-1}
        int bi = tid >> 5, r = (tid >> 4) & 1, w = tid & 15;
        bufs[bi][(r ? (BR - 1) : 0) * ST + w] = 0;
    }

    // --- binarize own 128 rows into bufs[0] (warp ballots -> packed words) ---
    #pragma unroll 4
    for (int p = 0; p < (CROWS * Wn) / NTHR; ++p) {
        int idx = p * NTHR + tid;
        float v = in[idx];
        uint32_t bits = __ballot_sync(0xffffffffu, v > 0.5f);
        if ((tid & 31) == 0) {
            int r = idx >> 9;            // local row
            int w = (idx >> 5) & 15;
            bufs[0][(r + 1) * ST + w] = bits;
        }
    }
    __syncthreads();

    const int lrow  = tid >> 2;          // 0..127
    const int q     = tid & 3;
    const int wbase = q * 4;
    const int i     = lrow + 1;          // buffer row index (1..128)
    const bool topB = (lrow == 0)        && (rank > 0);
    const bool botB = (lrow == CROWS-1)  && (rank < CSIZE - 1);

    uint32_t R[4];
    #pragma unroll
    for (int w = 0; w < 4; ++w) R[w] = bufs[0][i * ST + wbase + w];

    int s = 0;
    int myLast = 0;

    for (;;) {
        ++s;
        uint32_t* cur = bufs[s & 1];
        __syncthreads();                 // (A) order prior compute's smem writes

        // ---- store phase ----
        if (myLast > s - 3) {
            #pragma unroll
            for (int w = 0; w < 4; ++w) cur[i * ST + wbase + w] = R[w];
            if (topB) {
                #pragma unroll
                for (int w = 0; w < 4; ++w)
                    st_cluster(smem_u32(&cur[(BR - 1) * ST + wbase + w]), rank - 1, R[w]);
            }
            if (botB) {
                #pragma unroll
                for (int w = 0; w < 4; ++w)
                    st_cluster(smem_u32(&cur[0 * ST + wbase + w]), rank + 1, R[w]);
            }
        }
        // transmit own-row stamp of previous sub-iteration to neighbor halo
        if (q == 0) {
            const int pp = (s - 1) & 1;
            int stamp = s_chg[pp][i];
            if (topB) st_cluster(smem_u32(&s_chg[pp][BR - 1]), rank - 1, (uint32_t)stamp);
            if (botB) st_cluster(smem_u32(&s_chg[pp][0]),      rank + 1, (uint32_t)stamp);
        }
        // broadcast "changed at s-1" to all CTAs of the cluster
        if (tid == 0 && s_changed == s - 1) {
            uint32_t a = smem_u32(&c_changed);
            #pragma unroll
            for (int c = 0; c < CSIZE; ++c) st_cluster(a, c, (uint32_t)(s - 1));
        }
        CLUSTER_SYNC();                  // (B)

        if (c_changed <= s - 3) break;   // no removal in sub-iters s-1, s-2

        // ---- compute phase ----
        const int pb = (s - 1) & 1, ps = s - 1;
        bool dirty = (s_chg[pb][i] == ps) | (s_chg[pb][i - 1] == ps) | (s_chg[pb][i + 1] == ps);
        if (!dirty) continue;

        const int sub = (s + 1) & 1;     // s odd -> sub 0 ; s even -> sub 1
        const uint32_t* rU = &cur[(i - 1) * ST];
        const uint32_t* rO = &cur[i * ST];
        const uint32_t* rD = &cur[(i + 1) * ST];

        uint32_t aP = wbase ? rU[wbase - 1] : 0u;
        uint32_t cP = wbase ? rO[wbase - 1] : 0u;
        uint32_t bP = wbase ? rD[wbase - 1] : 0u;
        uint32_t aC = rU[wbase];
        uint32_t cC = R[0];
        uint32_t bC = rD[wbase];
        uint32_t cRight = (q < 3) ? rO[wbase + 4] : 0u;

        uint32_t removed = 0;
        uint32_t nR[4];
        #pragma unroll
        for (int w = 0; w < 4; ++w) {
            const int gw = wbase + w;
            uint32_t aN = 0, bN = 0, cN;
            if (gw < WPR - 1) { aN = rU[gw + 1]; bN = rD[gw + 1]; }
            cN = (w < 3) ? R[w + 1] : cRight;

            // P2..P9 clockwise from North
            uint32_t n0 = aC;
            uint32_t n1 = (aC >> 1) | (aN << 31);
            uint32_t n2 = (cC >> 1) | (cN << 31);
            uint32_t n3 = (bC >> 1) | (bN << 31);
            uint32_t n4 = bC;
            uint32_t n5 = (bC << 1) | (bP >> 31);
            uint32_t n6 = (cC << 1) | (cP >> 31);
            uint32_t n7 = (aC << 1) | (aP >> 31);

            // A == 1 (exactly one 0->1 transition around the ring)
            uint32_t e0 = ~n0 & n1, e1 = ~n1 & n2, e2 = ~n2 & n3, e3 = ~n3 & n4;
            uint32_t e4 = ~n4 & n5, e5 = ~n5 & n6, e6 = ~n6 & n7, e7 = ~n7 & n0;
            uint32_t one = e0, more = 0;
            more |= one & e1; one |= e1;
            more |= one & e2; one |= e2;
            more |= one & e3; one |= e3;
            more |= one & e4; one |= e4;
            more |= one & e5; one |= e5;
            more |= one & e6; one |= e6;
            more |= one & e7; one |= e7;
            uint32_t A1 = one & ~more;

            // Bn >= 2
            uint32_t o2 = n0, m2 = 0;
            m2 |= o2 & n1; o2 |= n1;
            m2 |= o2 & n2; o2 |= n2;
            m2 |= o2 & n3; o2 |= n3;
            m2 |= o2 & n4; o2 |= n4;
            m2 |= o2 & n5; o2 |= n5;
            m2 |= o2 & n6; o2 |= n6;
            m2 |= o2 & n7; o2 |= n7;
            uint32_t ge2 = m2;

            // Bn <= 6 (at least 2 neighbors zero)
            uint32_t z, oz = ~n0, mz = 0;
            z = ~n1; mz |= oz & z; oz |= z;
            z = ~n2; mz |= oz & z; oz |= z;
            z = ~n3; mz |= oz & z; oz |= z;
            z = ~n4; mz |= oz & z; oz |= z;
            z = ~n5; mz |= oz & z; oz |= z;
            z = ~n6; mz |= oz & z; oz |= z;
            z = ~n7; mz |= oz & z; oz |= z;
            uint32_t le6 = mz;

            uint32_t cond = A1 & ge2 & le6;
            if (sub == 0)
                cond &= ~(n0 & n2 & n4) & ~(n2 & n4 & n6);
            else
                cond &= ~(n0 & n2 & n6) & ~(n0 & n4 & n6);

            removed |= cC & cond;
            nR[w] = cC & ~cond;

            aP = aC; aC = aN;
            cP = cC; cC = cN;
            bP = bC; bC = bN;
        }
        #pragma unroll
        for (int w = 0; w < 4; ++w) R[w] = nR[w];
        if (removed) {
            s_chg[s & 1][i] = s;
            s_changed = s;
            myLast = s;
        }
    }

    // ---- write out bit-packed skeleton from registers ----
    const int grow = (int)rank * CROWS + lrow;
    #pragma unroll
    for (int w = 0; w < 4; ++w)
        g_skel[m][b][grow][wbase + w] = R[w];

    // ---- per-batch rendezvous (16 CTAs: 8 pred + 8 gt... 4+4) ----
    __threadfence();
    __syncthreads();                      // all skeleton stores issued + fenced
    if (tid == 0) {
        if (m == 0 && rank == 0) {        // designated zeroer for this batch
            g_counts[b][0] = 0; g_counts[b][1] = 0; g_counts[b][2] = 0;
            __threadfence();
        }
        atomicAdd(&g_bt[b], 1);           // monotonic across graph replays
        while ((((volatile int*)g_bt)[b] & 7) != 0) __nanosleep(64);
        __threadfence();                  // acquire: see all 8 CTAs' writes
    }
    __syncthreads();

    // ---- parallel counting: this CTA counts a 64-row strip of batch b ----
    const int cidx = m * CSIZE + (int)rank;     // 0..7
    const int base = cidx * STRIP - 3;
    uint32_t* sP = &bufs[0][0];                 // reuse smem (CR*ST <= BR*ST)
    uint32_t* sG = &bufs[1][0];
    const uint32_t* P = &g_skel[0][b][0][0];
    const uint32_t* G = &g_skel[1][b][0][0];

    for (int idx = tid; idx < CR * WPR; idx += NTHR) {
        int r = idx >> 4, w = idx & 15;
        int gr = base + r;
        bool ok = (gr >= 0) & (gr < Hn);
        sP[r * ST + w] = ok ? P[gr * WPR + w] : 0u;
        sG[r * ST + w] = ok ? G[gr * WPR + w] : 0u;
    }
    __syncthreads();

    int tp = 0, fp = 0, fn = 0;
    #pragma unroll
    for (int u = 0; u < 2; ++u) {
        int e  = tid + u * NTHR;        // 0..1023 -> 64 rows x 16 words
        int rl = (e >> 4) + 3;          // window row 3..66
        int wc = e & 15;
        uint32_t dg = dil3w(sG, rl, wc);
        uint32_t dp = dil3w(sP, rl, wc);
        uint32_t pw = sP[rl * ST + wc];
        uint32_t gw = sG[rl * ST + wc];
        tp += __popc(pw & dg);
        fp += __popc(pw & ~dg);
        fn += __popc(gw & ~dp);
    }

    if (tid == 0) { stp = 0; sfp = 0; sfn = 0; }
    __syncthreads();
    #pragma unroll
    for (int o = 16; o > 0; o >>= 1) {
        tp += __shfl_down_sync(0xffffffffu, tp, o);
        fp += __shfl_down_sync(0xffffffffu, fp, o);
        fn += __shfl_down_sync(0xffffffffu, fn, o);
    }
    if ((tid & 31) == 0) {
        atomicAdd(&stp, tp);
        atomicAdd(&sfp, fp);
        atomicAdd(&sfn, fn);
    }
    __syncthreads();

    if (tid == 0) {
        atomicAdd(&g_counts[b][0], stp);
        atomicAdd(&g_counts[b][1], sfp);
        atomicAdd(&g_counts[b][2], sfn);
        __threadfence();
        int t = atomicAdd(&g_ticket, 1) & 127;   // 128 CTAs total
        if (t == 127) {                           // last CTA finalizes
            __threadfence();
            float s0 = 0.f, s1 = 0.f, s2 = 0.f;
            for (int bb = 0; bb < BATCH; ++bb) {
                float TP = (float)g_counts[bb][0];
                float FP = (float)g_counts[bb][1];
                float FN = (float)g_counts[bb][2];
                s0 += TP / (TP + FP + 1e-12f);
                s1 += TP / (TP + FN + 1e-12f);
                s2 += TP / (TP + FP + FN + 1e-12f);
            }
            out[0] = s0 * (1.0f / BATCH);
            out[1] = s1 * (1.0f / BATCH);
            out[2] = s2 * (1.0f / BATCH);
        }
    }
}

extern "C" void kernel_launch(void* const* d_in, const int* in_sizes, int n_in,
                              void* d_out, int out_size) {
    (void)in_sizes; (void)n_in; (void)out_size;
    const float* pred = (const float*)d_in[0];
    const float* gt   = (const float*)d_in[1];
    skel_kernel<<<2 * BATCH * CSIZE, NTHR>>>(pred, gt, (float*)d_out);
}

// round 9
// speedup vs baseline: 1.5172x; 1.1088x over previous
#include <cuda_runtime.h>
#include <cstdint>

#define BATCH 16
#define Hn 512
#define Wn 512
#define WPR 16            // 32-bit words per row
#define ST 17             // smem row stride (bank padding)
#define CSIZE 4           // cluster size (CTAs per image)
#define CROWS (Hn / CSIZE)   // 128 rows per CTA
#define BR (CROWS + 2)       // rows incl. top/bottom halo
#define NTHR 1024            // 8 threads per row, 2 words each
#define WPT 2                // words per thread

// counting: each of the 8 CTAs per batch counts a 64-row strip (+3 halo)
#define STRIP 64
#define CR (STRIP + 6)       // 70-row window

__device__ uint32_t g_skel[2][BATCH][Hn][WPR];
__device__ int g_counts[BATCH][3];     // integer partials (deterministic)
__device__ int g_bt[BATCH];            // per-batch arrival tickets (monotonic)
__device__ int g_ticket;               // finalize ticket (monotonic, &127)

// ---------------------------------------------------------------------------
// helpers
// ---------------------------------------------------------------------------
__device__ __forceinline__ uint32_t smem_u32(const void* p) {
    uint32_t a;
    asm("{ .reg .u64 t; cvta.to.shared.u64 t, %1; cvt.u32.u64 %0, t; }"
        : "=r"(a) : "l"(p));
    return a;
}
__device__ __forceinline__ void st_cluster(uint32_t laddr, uint32_t rank, uint32_t val) {
    asm volatile(
        "{ .reg .b32 ra; mapa.shared::cluster.u32 ra, %0, %1; "
        "st.shared::cluster.u32 [ra], %2; }"
        :: "r"(laddr), "r"(rank), "r"(val) : "memory");
}
__device__ __forceinline__ uint32_t cluster_rank() {
    uint32_t r; asm("mov.u32 %0, %%cluster_ctarank;" : "=r"(r)); return r;
}
#define CLUSTER_SYNC() do { \
    asm volatile("barrier.cluster.arrive.aligned;" ::: "memory"); \
    asm volatile("barrier.cluster.wait.aligned;"   ::: "memory"); \
} while (0)

// horizontal dilations on an ST-strided window
__device__ __forceinline__ uint32_t hd3(const uint32_t* M, int r, int w) {
    uint32_t p = (w > 0)       ? M[r * ST + w - 1] : 0u;
    uint32_t c =                 M[r * ST + w];
    uint32_t n = (w < WPR - 1) ? M[r * ST + w + 1] : 0u;
    uint32_t v = c;
    v |= (c >> 1) | (n << 31); v |= (c << 1) | (p >> 31);
    v |= (c >> 2) | (n << 30); v |= (c << 2) | (p >> 30);
    v |= (c >> 3) | (n << 29); v |= (c << 3) | (p >> 29);
    return v;
}
__device__ __forceinline__ uint32_t hd2(const uint32_t* M, int r, int w) {
    uint32_t p = (w > 0)       ? M[r * ST + w - 1] : 0u;
    uint32_t c =                 M[r * ST + w];
    uint32_t n = (w < WPR - 1) ? M[r * ST + w + 1] : 0u;
    uint32_t v = c;
    v |= (c >> 1) | (n << 31); v |= (c << 1) | (p >> 31);
    v |= (c >> 2) | (n << 30); v |= (c << 2) | (p >> 30);
    return v;
}
__device__ __forceinline__ uint32_t dil3w(const uint32_t* M, int r, int w) {
    // squared radius 9: dy=0 -> |dx|<=3; |dy| in {1,2} -> |dx|<=2; |dy|=3 -> dx=0
    uint32_t v = hd3(M, r, w);
    v |= hd2(M, r - 1, w) | hd2(M, r + 1, w);
    v |= hd2(M, r - 2, w) | hd2(M, r + 2, w);
    v |= M[(r - 3) * ST + w] | M[(r + 3) * ST + w];
    return v;
}

// ---------------------------------------------------------------------------
// Fused kernel: binarize + Zhang-Suen to convergence (4-CTA cluster per
// image), then PARALLEL per-strip counting after a per-batch spin rendezvous.
// ---------------------------------------------------------------------------
__global__ void __launch_bounds__(NTHR, 1) __cluster_dims__(CSIZE, 1, 1)
skel_kernel(const float* __restrict__ pred, const float* __restrict__ gt,
            float* __restrict__ out) {
    __shared__ uint32_t bufs[2][BR * ST];
    __shared__ int s_chg[2][BR];     // stamp of last change per row, by parity
    __shared__ int s_changed;        // local: max stamp with any removal
    __shared__ int c_changed;        // cluster: max stamp with any removal
    __shared__ int stp, sfp, sfn;

    const int tid = threadIdx.x;
    const uint32_t rank = cluster_rank();
    const int img = blockIdx.x >> 2;
    const int b = img & 15;
    const int m = img >> 4;          // 0 = pred, 1 = gt
    const float* in = (m ? gt : pred) + (size_t)b * Hn * Wn + (size_t)rank * CROWS * Wn;

    // init stamps, flags, halo rows (halos stay 0 forever on image edges)
    if (tid < BR) { s_chg[0][tid] = 0; s_chg[1][tid] = 0; }
    if (tid == 0) { s_changed = 0; c_changed = 0; }
    if (tid < 2 * 2 * WPR) {          // 64 halo words: 2 bufs x {row 0, row BR-1}
        int bi = tid >> 5, r = (tid >> 4) & 1, w = tid & 15;
        bufs[bi][(r ? (BR - 1) : 0) * ST + w] = 0;
    }

    // --- binarize own 128 rows into bufs[0] (warp ballots -> packed words) ---
    #pragma unroll 4
    for (int p = 0; p < (CROWS * Wn) / NTHR; ++p) {
        int idx = p * NTHR + tid;
        float v = in[idx];
        uint32_t bits = __ballot_sync(0xffffffffu, v > 0.5f);
        if ((tid & 31) == 0) {
            int r = idx >> 9;            // local row
            int w = (idx >> 5) & 15;
            bufs[0][(r + 1) * ST + w] = bits;
        }
    }
    __syncthreads();

    const int lrow  = tid >> 3;          // 0..127
    const int q     = tid & 7;
    const int wbase = q * WPT;
    const int i     = lrow + 1;          // buffer row index (1..128)
    const bool topB = (lrow == 0)        && (rank > 0);
    const bool botB = (lrow == CROWS-1)  && (rank < CSIZE - 1);

    uint32_t R[WPT];
    #pragma unroll
    for (int w = 0; w < WPT; ++w) R[w] = bufs[0][i * ST + wbase + w];

    int s = 0;
    int myLast = 0;

    for (;;) {
        ++s;
        uint32_t* cur = bufs[s & 1];
        __syncthreads();                 // (A) order prior compute's s_chg writes

        // ---- store phase ----
        if (myLast > s - 3) {
            #pragma unroll
            for (int w = 0; w < WPT; ++w) cur[i * ST + wbase + w] = R[w];
            if (topB) {
                #pragma unroll
                for (int w = 0; w < WPT; ++w)
                    st_cluster(smem_u32(&cur[(BR - 1) * ST + wbase + w]), rank - 1, R[w]);
            }
            if (botB) {
                #pragma unroll
                for (int w = 0; w < WPT; ++w)
                    st_cluster(smem_u32(&cur[0 * ST + wbase + w]), rank + 1, R[w]);
            }
        }
        // transmit own-row stamp of previous sub-iteration to neighbor halo
        if (q == 0) {
            const int pp = (s - 1) & 1;
            int stamp = s_chg[pp][i];
            if (topB) st_cluster(smem_u32(&s_chg[pp][BR - 1]), rank - 1, (uint32_t)stamp);
            if (botB) st_cluster(smem_u32(&s_chg[pp][0]),      rank + 1, (uint32_t)stamp);
        }
        // broadcast "changed at s-1" to all CTAs of the cluster
        if (tid == 0 && s_changed == s - 1) {
            uint32_t a = smem_u32(&c_changed);
            #pragma unroll
            for (int c = 0; c < CSIZE; ++c) st_cluster(a, c, (uint32_t)(s - 1));
        }
        CLUSTER_SYNC();                  // (B)

        if (c_changed <= s - 3) break;   // no removal in sub-iters s-1, s-2

        // ---- compute phase ----
        const int pb = (s - 1) & 1, ps = s - 1;
        bool dirty = (s_chg[pb][i] == ps) | (s_chg[pb][i - 1] == ps) | (s_chg[pb][i + 1] == ps);
        if (!dirty) continue;

        const int sub = (s + 1) & 1;     // s odd -> sub 0 ; s even -> sub 1
        const uint32_t* rU = &cur[(i - 1) * ST];
        const uint32_t* rO = &cur[i * ST];
        const uint32_t* rD = &cur[(i + 1) * ST];

        uint32_t aP = wbase ? rU[wbase - 1] : 0u;
        uint32_t cP = wbase ? rO[wbase - 1] : 0u;
        uint32_t bP = wbase ? rD[wbase - 1] : 0u;
        uint32_t aC = rU[wbase];
        uint32_t cC = R[0];
        uint32_t bC = rD[wbase];
        uint32_t cRight = (q < 7) ? rO[wbase + WPT] : 0u;

        uint32_t removed = 0;
        uint32_t nR[WPT];
        #pragma unroll
        for (int w = 0; w < WPT; ++w) {
            const int gw = wbase + w;
            uint32_t aN = 0, bN = 0, cN;
            if (gw < WPR - 1) { aN = rU[gw + 1]; bN = rD[gw + 1]; }
            cN = (w < WPT - 1) ? R[w + 1] : cRight;

            // P2..P9 clockwise from North
            uint32_t n0 = aC;
            uint32_t n1 = (aC >> 1) | (aN << 31);
            uint32_t n2 = (cC >> 1) | (cN << 31);
            uint32_t n3 = (bC >> 1) | (bN << 31);
            uint32_t n4 = bC;
            uint32_t n5 = (bC << 1) | (bP >> 31);
            uint32_t n6 = (cC << 1) | (cP >> 31);
            uint32_t n7 = (aC << 1) | (aP >> 31);

            // A == 1 (exactly one 0->1 transition around the ring)
            uint32_t e0 = ~n0 & n1, e1 = ~n1 & n2, e2 = ~n2 & n3, e3 = ~n3 & n4;
            uint32_t e4 = ~n4 & n5, e5 = ~n5 & n6, e6 = ~n6 & n7, e7 = ~n7 & n0;
            uint32_t one = e0, more = 0;
            more |= one & e1; one |= e1;
            more |= one & e2; one |= e2;
            more |= one & e3; one |= e3;
            more |= one & e4; one |= e4;
            more |= one & e5; one |= e5;
            more |= one & e6; one |= e6;
            more |= one & e7; one |= e7;
            uint32_t A1 = one & ~more;

            // Bn >= 2
            uint32_t o2 = n0, m2 = 0;
            m2 |= o2 & n1; o2 |= n1;
            m2 |= o2 & n2; o2 |= n2;
            m2 |= o2 & n3; o2 |= n3;
            m2 |= o2 & n4; o2 |= n4;
            m2 |= o2 & n5; o2 |= n5;
            m2 |= o2 & n6; o2 |= n6;
            m2 |= o2 & n7; o2 |= n7;
            uint32_t ge2 = m2;

            // Bn <= 6 (at least 2 neighbors zero)
            uint32_t z, oz = ~n0, mz = 0;
            z = ~n1; mz |= oz & z; oz |= z;
            z = ~n2; mz |= oz & z; oz |= z;
            z = ~n3; mz |= oz & z; oz |= z;
            z = ~n4; mz |= oz & z; oz |= z;
            z = ~n5; mz |= oz & z; oz |= z;
            z = ~n6; mz |= oz & z; oz |= z;
            z = ~n7; mz |= oz & z; oz |= z;
            uint32_t le6 = mz;

            uint32_t cond = A1 & ge2 & le6;
            if (sub == 0)
                cond &= ~(n0 & n2 & n4) & ~(n2 & n4 & n6);
            else
                cond &= ~(n0 & n2 & n6) & ~(n0 & n4 & n6);

            removed |= cC & cond;
            nR[w] = cC & ~cond;

            aP = aC; aC = aN;
            cP = cC; cC = cN;
            bP = bC; bC = bN;
        }
        #pragma unroll
        for (int w = 0; w < WPT; ++w) R[w] = nR[w];
        if (removed) {
            s_chg[s & 1][i] = s;
            s_changed = s;
            myLast = s;
        }
    }

    // ---- write out bit-packed skeleton from registers ----
    const int grow = (int)rank * CROWS + lrow;
    #pragma unroll
    for (int w = 0; w < WPT; ++w)
        g_skel[m][b][grow][wbase + w] = R[w];

    // ---- per-batch rendezvous (8 CTAs per batch) ----
    __threadfence();
    __syncthreads();                      // all skeleton stores issued + fenced
    if (tid == 0) {
        if (m == 0 && rank == 0) {        // designated zeroer for this batch
            g_counts[b][0] = 0; g_counts[b][1] = 0; g_counts[b][2] = 0;
            __threadfence();
        }
        atomicAdd(&g_bt[b], 1);           // monotonic across graph replays
        while ((((volatile int*)g_bt)[b] & 7) != 0) __nanosleep(64);
        __threadfence();                  // acquire: see all 8 CTAs' writes
    }
    __syncthreads();

    // ---- parallel counting: this CTA counts a 64-row strip of batch b ----
    const int cidx = m * CSIZE + (int)rank;     // 0..7
    const int base = cidx * STRIP - 3;
    uint32_t* sP = &bufs[0][0];                 // reuse smem (CR*ST <= BR*ST)
    uint32_t* sG = &bufs[1][0];
    const uint32_t* P = &g_skel[0][b][0][0];
    const uint32_t* G = &g_skel[1][b][0][0];

    for (int idx = tid; idx < CR * WPR; idx += NTHR) {
        int r = idx >> 4, w = idx & 15;
        int gr = base + r;
        bool ok = (gr >= 0) & (gr < Hn);
        sP[r * ST + w] = ok ? P[gr * WPR + w] : 0u;
        sG[r * ST + w] = ok ? G[gr * WPR + w] : 0u;
    }
    __syncthreads();

    // 64 rows x 16 words = 1024 elements: exactly one per thread
    const int rl = (tid >> 4) + 3;      // window row 3..66
    const int wc = tid & 15;
    uint32_t dg = dil3w(sG, rl, wc);
    uint32_t dp = dil3w(sP, rl, wc);
    uint32_t pw = sP[rl * ST + wc];
    uint32_t gw = sG[rl * ST + wc];
    int tp = __popc(pw & dg);
    int fp = __popc(pw & ~dg);
    int fn = __popc(gw & ~dp);

    if (tid == 0) { stp = 0; sfp = 0; sfn = 0; }
    __syncthreads();
    #pragma unroll
    for (int o = 16; o > 0; o >>= 1) {
        tp += __shfl_down_sync(0xffffffffu, tp, o);
        fp += __shfl_down_sync(0xffffffffu, fp, o);
        fn += __shfl_down_sync(0xffffffffu, fn, o);
    }
    if ((tid & 31) == 0) {
        atomicAdd(&stp, tp);
        atomicAdd(&sfp, fp);
        atomicAdd(&sfn, fn);
    }
    __syncthreads();

    if (tid == 0) {
        atomicAdd(&g_counts[b][0], stp);
        atomicAdd(&g_counts[b][1], sfp);
        atomicAdd(&g_counts[b][2], sfn);
        __threadfence();
        int t = atomicAdd(&g_ticket, 1) & 127;   // 128 CTAs total
        if (t == 127) {                           // last CTA finalizes
            __threadfence();
            float s0 = 0.f, s1 = 0.f, s2 = 0.f;
            for (int bb = 0; bb < BATCH; ++bb) {
                float TP = (float)g_counts[bb][0];
                float FP = (float)g_counts[bb][1];
                float FN = (float)g_counts[bb][2];
                s0 += TP / (TP + FP + 1e-12f);
                s1 += TP / (TP + FN + 1e-12f);
                s2 += TP / (TP + FP + FN + 1e-12f);
            }
            out[0] = s0 * (1.0f / BATCH);
            out[1] = s1 * (1.0f / BATCH);
            out[2] = s2 * (1.0f / BATCH);
        }
    }
}

extern "C" void kernel_launch(void* const* d_in, const int* in_sizes, int n_in,
                              void* d_out, int out_size) {
    (void)in_sizes; (void)n_in; (void)out_size;
    const float* pred = (const float*)d_in[0];
    const float* gt   = (const float*)d_in[1];
    skel_kernel<<<2 * BATCH * CSIZE, NTHR>>>(pred, gt, (float*)d_out);
}